// round 3
// baseline (speedup 1.0000x reference)
#include <cuda_runtime.h>
#include <math.h>

// ---------------- problem constants ----------------
#define BATCH 4
#define CCH   512
#define C8    64
#define NPIX  4096           // 64*64
// ---------------- scratch (device globals; allocation-free) ----------------
__device__ float g_qp[BATCH * C8 * NPIX];          // PAM q   [B,64,N]
__device__ float g_kp[BATCH * C8 * NPIX];          // PAM k   [B,64,N]
__device__ float g_vp[BATCH * CCH * NPIX];         // PAM v   [B,512,N]
__device__ float g_qc[BATCH * C8 * NPIX];          // CAM q   (== [B,512,512] view)
__device__ float g_kc[BATCH * C8 * NPIX];          // CAM k
__device__ float g_vc[BATCH * CCH * NPIX];         // CAM v
__device__ float g_attn[(size_t)BATCH * NPIX * NPIX];  // PAM energy/attn, 268 MB
__device__ float g_ec[BATCH * CCH * CCH];          // CAM energy/attn
__device__ float g_outp[BATCH * CCH * NPIX];       // PAM out (pre-gamma)
__device__ float g_outc[BATCH * CCH * NPIX];       // CAM out (pre-gamma)

// ---------------- generic tiled SIMT fp32 GEMM ----------------
// C[M,N] = A * B (+bias per row), per-batch strides via grid.z.
// TA: A stored [K,M] (use A[k*M+m]); else row-major [M,K].
// TB: B stored [N,K] (use B[n*K+k]); else row-major [K,N].
template<bool TA, bool TB, bool BIAS>
__global__ void __launch_bounds__(256)
gemm128(const float* __restrict__ A, const float* __restrict__ B,
        const float* __restrict__ bias, float* __restrict__ C,
        int M, int N, int K,
        long long aStr, long long bStr, long long cStr)
{
    constexpr int BM = 128, BN = 128, BK = 8, TM = 8, TN = 8;
    constexpr int THREADS = 256;
    __shared__ float As[BK][BM + 4];
    __shared__ float Bs[BK][BN + 4];

    const float* Ab = A + (long long)blockIdx.z * aStr;
    const float* Bb = B + (long long)blockIdx.z * bStr;
    float*       Cb = C + (long long)blockIdx.z * cStr;

    const int bm = blockIdx.y * BM;
    const int bn = blockIdx.x * BN;
    const int tid  = threadIdx.x;
    const int tcol = tid & 15;    // BN/TN = 16
    const int trow = tid >> 4;    // BM/TM = 16

    float acc[TM][TN];
#pragma unroll
    for (int i = 0; i < TM; i++)
#pragma unroll
        for (int j = 0; j < TN; j++) acc[i][j] = 0.0f;

    for (int k0 = 0; k0 < K; k0 += BK) {
        // load A tile (coalesced along the stored-contiguous dim)
#pragma unroll
        for (int t = 0; t < (BM * BK) / THREADS; t++) {
            int i = tid + t * THREADS;
            int m, kk;
            if (TA) { m = i % BM; kk = i / BM; }
            else    { kk = i % BK; m = i / BK; }
            int gm = bm + m, gk = k0 + kk;
            float v = 0.0f;
            if (gm < M && gk < K)
                v = TA ? Ab[(long long)gk * M + gm] : Ab[(long long)gm * K + gk];
            As[kk][m] = v;
        }
        // load B tile
#pragma unroll
        for (int t = 0; t < (BK * BN) / THREADS; t++) {
            int i = tid + t * THREADS;
            int n, kk;
            if (TB) { kk = i % BK; n = i / BK; }
            else    { n = i % BN; kk = i / BN; }
            int gn = bn + n, gk = k0 + kk;
            float v = 0.0f;
            if (gn < N && gk < K)
                v = TB ? Bb[(long long)gn * K + gk] : Bb[(long long)gk * N + gn];
            Bs[kk][n] = v;
        }
        __syncthreads();
#pragma unroll
        for (int kk = 0; kk < BK; kk++) {
            float ar[TM], br[TN];
#pragma unroll
            for (int i = 0; i < TM; i++) ar[i] = As[kk][trow * TM + i];
#pragma unroll
            for (int j = 0; j < TN; j++) br[j] = Bs[kk][tcol * TN + j];
#pragma unroll
            for (int i = 0; i < TM; i++)
#pragma unroll
                for (int j = 0; j < TN; j++)
                    acc[i][j] = fmaf(ar[i], br[j], acc[i][j]);
        }
        __syncthreads();
    }

    // store (vectorized; all our N are multiples of 128 so fast path always hits)
#pragma unroll
    for (int i = 0; i < TM; i++) {
        int gm = bm + trow * TM + i;
        if (gm >= M) continue;
        float bv = BIAS ? bias[gm] : 0.0f;
#pragma unroll
        for (int j = 0; j < TN; j += 4) {
            int gn = bn + tcol * TN + j;
            if (gn + 3 < N) {
                float4 v;
                v.x = acc[i][j + 0] + bv;
                v.y = acc[i][j + 1] + bv;
                v.z = acc[i][j + 2] + bv;
                v.w = acc[i][j + 3] + bv;
                *reinterpret_cast<float4*>(&Cb[(long long)gm * N + gn]) = v;
            } else {
                for (int jj = 0; jj < 4; jj++)
                    if (gn + jj < N) Cb[(long long)gm * N + gn + jj] = acc[i][j + jj] + bv;
            }
        }
    }
}

// ---------------- row softmax (in place). flip=1: softmax(rowmax - e) == exp(min-e)/sum ----
__global__ void __launch_bounds__(256)
softmax_rows(float* __restrict__ data, int n, int flip)
{
    __shared__ float buf[4096];
    __shared__ float red[8];
    __shared__ float bcast;
    const long long row = blockIdx.x;
    float* p = data + row * (long long)n;
    const int tid = threadIdx.x;
    const int lane = tid & 31, wid = tid >> 5;

    float m = flip ? 3.0e38f : -3.0e38f;
    for (int i = tid; i < n; i += 256) {
        float v = p[i];
        buf[i] = v;
        m = flip ? fminf(m, v) : fmaxf(m, v);
    }
#pragma unroll
    for (int o = 16; o > 0; o >>= 1) {
        float t = __shfl_xor_sync(0xffffffffu, m, o);
        m = flip ? fminf(m, t) : fmaxf(m, t);
    }
    if (lane == 0) red[wid] = m;
    __syncthreads();
    if (wid == 0) {
        float v = (lane < 8) ? red[lane] : (flip ? 3.0e38f : -3.0e38f);
#pragma unroll
        for (int o = 4; o > 0; o >>= 1) {
            float t = __shfl_xor_sync(0xffffffffu, v, o);
            v = flip ? fminf(v, t) : fmaxf(v, t);
        }
        if (lane == 0) bcast = v;
    }
    __syncthreads();
    const float mx = bcast;

    float s = 0.0f;
    for (int i = tid; i < n; i += 256) {
        float e = __expf(flip ? (mx - buf[i]) : (buf[i] - mx));
        buf[i] = e;
        s += e;
    }
#pragma unroll
    for (int o = 16; o > 0; o >>= 1) s += __shfl_xor_sync(0xffffffffu, s, o);
    if (lane == 0) red[wid] = s;
    __syncthreads();
    if (wid == 0) {
        float v = (lane < 8) ? red[lane] : 0.0f;
#pragma unroll
        for (int o = 4; o > 0; o >>= 1) v += __shfl_xor_sync(0xffffffffu, v, o);
        if (lane == 0) bcast = v;
    }
    __syncthreads();
    const float inv = 1.0f / bcast;
    for (int i = tid; i < n; i += 256) p[i] = buf[i] * inv;
}

// ---------------- epilogue: out = 2x + gp*outp + gc*outc ----------------
__global__ void __launch_bounds__(256)
combine_kernel(const float4* __restrict__ x, const float4* __restrict__ op,
               const float4* __restrict__ oc, const float* __restrict__ pg,
               const float* __restrict__ cg, float4* __restrict__ out, int n4)
{
    int i = blockIdx.x * blockDim.x + threadIdx.x;
    if (i >= n4) return;
    const float a = pg[0], b = cg[0];
    float4 xv = x[i], pv = op[i], cv = oc[i];
    float4 r;
    r.x = 2.0f * xv.x + a * pv.x + b * cv.x;
    r.y = 2.0f * xv.y + a * pv.y + b * cv.y;
    r.z = 2.0f * xv.z + a * pv.z + b * cv.z;
    r.w = 2.0f * xv.w + a * pv.w + b * cv.w;
    out[i] = r;
}

// ---------------- launch ----------------
extern "C" void kernel_launch(void* const* d_in, const int* in_sizes, int n_in,
                              void* d_out, int out_size)
{
    (void)in_sizes; (void)n_in; (void)out_size;
    const float* x       = (const float*)d_in[0];
    const float* pam_wq  = (const float*)d_in[1];
    const float* pam_bq  = (const float*)d_in[2];
    const float* pam_wk  = (const float*)d_in[3];
    const float* pam_bk  = (const float*)d_in[4];
    const float* pam_wv  = (const float*)d_in[5];
    const float* pam_bv  = (const float*)d_in[6];
    const float* pam_g   = (const float*)d_in[7];
    const float* cam_wq  = (const float*)d_in[8];
    const float* cam_bq  = (const float*)d_in[9];
    const float* cam_wk  = (const float*)d_in[10];
    const float* cam_bk  = (const float*)d_in[11];
    const float* cam_wv  = (const float*)d_in[12];
    const float* cam_bv  = (const float*)d_in[13];
    const float* cam_g   = (const float*)d_in[14];

    float *qp, *kp, *vp, *qc, *kc, *vc, *attn, *ec, *outp, *outc;
    cudaGetSymbolAddress((void**)&qp,   g_qp);
    cudaGetSymbolAddress((void**)&kp,   g_kp);
    cudaGetSymbolAddress((void**)&vp,   g_vp);
    cudaGetSymbolAddress((void**)&qc,   g_qc);
    cudaGetSymbolAddress((void**)&kc,   g_kc);
    cudaGetSymbolAddress((void**)&vc,   g_vc);
    cudaGetSymbolAddress((void**)&attn, g_attn);
    cudaGetSymbolAddress((void**)&ec,   g_ec);
    cudaGetSymbolAddress((void**)&outp, g_outp);
    cudaGetSymbolAddress((void**)&outc, g_outc);

    const long long xStr  = (long long)CCH * NPIX;     // per-batch x stride
    const long long qStr  = (long long)C8  * NPIX;     // 64*4096 (== 512*512)
    const long long vStr  = (long long)CCH * NPIX;
    const long long aStrP = (long long)NPIX * NPIX;    // PAM attn per batch
    const long long eStrC = (long long)CCH * CCH;

    dim3 blk(256);

    // ---- 1. projections: C = W[M,512] * x[512,4096] + bias ----
    gemm128<false,false,true><<<dim3(NPIX/128, 1, BATCH), blk>>>(pam_wq, x, pam_bq, qp, C8,  NPIX, CCH, 0, xStr, qStr);
    gemm128<false,false,true><<<dim3(NPIX/128, 1, BATCH), blk>>>(pam_wk, x, pam_bk, kp, C8,  NPIX, CCH, 0, xStr, qStr);
    gemm128<false,false,true><<<dim3(NPIX/128, 4, BATCH), blk>>>(pam_wv, x, pam_bv, vp, CCH, NPIX, CCH, 0, xStr, vStr);
    gemm128<false,false,true><<<dim3(NPIX/128, 1, BATCH), blk>>>(cam_wq, x, cam_bq, qc, C8,  NPIX, CCH, 0, xStr, qStr);
    gemm128<false,false,true><<<dim3(NPIX/128, 1, BATCH), blk>>>(cam_wk, x, cam_bk, kc, C8,  NPIX, CCH, 0, xStr, qStr);
    gemm128<false,false,true><<<dim3(NPIX/128, 4, BATCH), blk>>>(cam_wv, x, cam_bv, vc, CCH, NPIX, CCH, 0, xStr, vStr);

    // ---- 2. PAM energy: E[q,k] = sum_d qp[d,q]*kp[d,k]   (TN, K=64) ----
    gemm128<true,false,false><<<dim3(NPIX/128, NPIX/128, BATCH), blk>>>(qp, kp, nullptr, attn,
        NPIX, NPIX, C8, qStr, qStr, aStrP);

    // ---- 3. PAM softmax over rows of 4096 ----
    softmax_rows<<<BATCH * NPIX, 256>>>(attn, NPIX, 0);

    // ---- 4. PAM AV: out[c,q] = sum_k vp[c,k]*attn[q,k]   (NT, K=4096) ----
    gemm128<false,true,false><<<dim3(NPIX/128, CCH/128, BATCH), blk>>>(vp, attn, nullptr, outp,
        CCH, NPIX, NPIX, vStr, aStrP, vStr);

    // ---- 5. CAM energy: E[i,j] = sum_m qc[i,m]*kc[j,m]   (NT, 512^3) ----
    gemm128<false,true,false><<<dim3(CCH/128, CCH/128, BATCH), blk>>>(qc, kc, nullptr, ec,
        CCH, CCH, CCH, qStr, qStr, eStrC);

    // ---- 6. CAM softmax of (rowmax - e)  == flipped softmax ----
    softmax_rows<<<BATCH * CCH, 256>>>(ec, CCH, 1);

    // ---- 7. CAM AV: out[c,n] = sum_d attn[c,d]*vc[d,n]   (NN) ----
    gemm128<false,false,false><<<dim3(NPIX/128, CCH/128, BATCH), blk>>>(ec, vc, nullptr, outc,
        CCH, NPIX, CCH, eStrC, vStr, vStr);

    // ---- 8. combine ----
    const int n4 = (BATCH * CCH * NPIX) / 4;   // 2,097,152 float4s
    combine_kernel<<<(n4 + 255) / 256, 256>>>((const float4*)x, (const float4*)outp,
        (const float4*)outc, pam_g, cam_g, (float4*)d_out, n4);
}

// round 4
// speedup vs baseline: 2.5989x; 2.5989x over previous
#include <cuda_runtime.h>
#include <math.h>
#include <stdint.h>

// ---------------- problem constants ----------------
#define BATCH 4
#define CCH   512
#define C8    64
#define NPIX  4096           // 64*64

// ---------------- scratch (device globals; allocation-free) ----------------
__device__ float g_qp[BATCH * C8 * NPIX];
__device__ float g_kp[BATCH * C8 * NPIX];
__device__ float g_vp[BATCH * CCH * NPIX];
__device__ float g_qc[BATCH * C8 * NPIX];
__device__ float g_kc[BATCH * C8 * NPIX];
__device__ float g_vc[BATCH * CCH * NPIX];
__device__ float g_attn[(size_t)BATCH * NPIX * NPIX];
__device__ float g_ec[BATCH * CCH * CCH];
__device__ float g_outp[BATCH * CCH * NPIX];
__device__ float g_outc[BATCH * CCH * NPIX];

__device__ __forceinline__ uint32_t f2tf32(float x) {
    uint32_t r;
    asm("cvt.rna.tf32.f32 %0, %1;" : "=r"(r) : "f"(x));
    return r;
}

#define MMA_TF32(acc, af, bf)                                               \
    asm volatile(                                                           \
        "mma.sync.aligned.m16n8k8.row.col.f32.tf32.tf32.f32 "               \
        "{%0,%1,%2,%3},{%4,%5,%6,%7},{%8,%9},{%0,%1,%2,%3};"                \
        : "+f"(acc[0]), "+f"(acc[1]), "+f"(acc[2]), "+f"(acc[3])            \
        : "r"(af[0]), "r"(af[1]), "r"(af[2]), "r"(af[3]),                   \
          "r"(bf[0]), "r"(bf[1]))

// ---------------- tf32 tensor-core GEMM ----------------
// C[M,N] = A*B (+bias per row).  TA: A stored [K,M]; else [M,K].
// TB: B stored [N,K]; else [K,N].  Requires: K%16==0, N%128==0.
// CTA tile 128x128, BK=16, 8 warps of 64x32, double-buffered smem.
template<bool TA, bool TB, bool BIAS>
__global__ void __launch_bounds__(256)
gemm_tc(const float* __restrict__ A, const float* __restrict__ B,
        const float* __restrict__ bias, float* __restrict__ C,
        int M, int N, int K,
        long long aStr, long long bStr, long long cStr)
{
    constexpr int BM = 128, BN = 128, BK = 16;
    __shared__ uint32_t As[2][BK][BM + 8];
    __shared__ uint32_t Bs[2][BK][BN + 8];

    const float* Ab = A + (long long)blockIdx.z * aStr;
    const float* Bb = B + (long long)blockIdx.z * bStr;
    float*       Cb = C + (long long)blockIdx.z * cStr;

    const int bm = blockIdx.y * BM;
    const int bn = blockIdx.x * BN;
    const int tid = threadIdx.x;
    const int lane = tid & 31;
    const int grp  = lane >> 2;      // 0..7
    const int tig  = lane & 3;       // 0..3
    const int warpId = tid >> 5;
    const int warpM  = warpId >> 2;  // 0..1  (64-row slabs)
    const int warpN  = warpId & 3;   // 0..3  (32-col slabs)

    float acc[4][4][4];
#pragma unroll
    for (int mi = 0; mi < 4; mi++)
#pragma unroll
        for (int ni = 0; ni < 4; ni++)
#pragma unroll
            for (int r = 0; r < 4; r++) acc[mi][ni][r] = 0.0f;

    float4 ra[2], rb[2];

    auto ldA = [&](int k0) {
#pragma unroll
        for (int i = 0; i < 2; i++) {
            int idx = tid + i * 256;
            if (TA) {
                int k = idx >> 5, m4 = idx & 31;
                int gm = bm + m4 * 4;
                ra[i] = (gm < M)
                    ? *reinterpret_cast<const float4*>(Ab + (long long)(k0 + k) * M + gm)
                    : make_float4(0.f, 0.f, 0.f, 0.f);
            } else {
                int m = idx >> 2, k4 = idx & 3;
                int gm = bm + m;
                ra[i] = (gm < M)
                    ? *reinterpret_cast<const float4*>(Ab + (long long)gm * K + k0 + k4 * 4)
                    : make_float4(0.f, 0.f, 0.f, 0.f);
            }
        }
    };
    auto stA = [&](int buf) {
#pragma unroll
        for (int i = 0; i < 2; i++) {
            int idx = tid + i * 256;
            float v[4] = {ra[i].x, ra[i].y, ra[i].z, ra[i].w};
            if (TA) {
                int k = idx >> 5, m4 = idx & 31;
#pragma unroll
                for (int j = 0; j < 4; j++) As[buf][k][m4 * 4 + j] = f2tf32(v[j]);
            } else {
                int m = idx >> 2, k4 = idx & 3;
#pragma unroll
                for (int j = 0; j < 4; j++) As[buf][k4 * 4 + j][m] = f2tf32(v[j]);
            }
        }
    };
    auto ldB = [&](int k0) {
#pragma unroll
        for (int i = 0; i < 2; i++) {
            int idx = tid + i * 256;
            if (TB) {
                int n = idx >> 2, k4 = idx & 3;
                rb[i] = *reinterpret_cast<const float4*>(Bb + (long long)(bn + n) * K + k0 + k4 * 4);
            } else {
                int k = idx >> 5, n4 = idx & 31;
                rb[i] = *reinterpret_cast<const float4*>(Bb + (long long)(k0 + k) * N + bn + n4 * 4);
            }
        }
    };
    auto stB = [&](int buf) {
#pragma unroll
        for (int i = 0; i < 2; i++) {
            int idx = tid + i * 256;
            float v[4] = {rb[i].x, rb[i].y, rb[i].z, rb[i].w};
            if (TB) {
                int n = idx >> 2, k4 = idx & 3;
#pragma unroll
                for (int j = 0; j < 4; j++) Bs[buf][k4 * 4 + j][n] = f2tf32(v[j]);
            } else {
                int k = idx >> 5, n4 = idx & 31;
#pragma unroll
                for (int j = 0; j < 4; j++) Bs[buf][k][n4 * 4 + j] = f2tf32(v[j]);
            }
        }
    };
    auto compute = [&](int buf) {
#pragma unroll
        for (int ks = 0; ks < BK; ks += 8) {
            uint32_t af[4][4], bf[4][2];
#pragma unroll
            for (int mi = 0; mi < 4; mi++) {
                int mB = warpM * 64 + mi * 16;
                af[mi][0] = As[buf][ks + tig    ][mB + grp];
                af[mi][1] = As[buf][ks + tig    ][mB + grp + 8];
                af[mi][2] = As[buf][ks + tig + 4][mB + grp];
                af[mi][3] = As[buf][ks + tig + 4][mB + grp + 8];
            }
#pragma unroll
            for (int ni = 0; ni < 4; ni++) {
                int nB = warpN * 32 + ni * 8;
                bf[ni][0] = Bs[buf][ks + tig    ][nB + grp];
                bf[ni][1] = Bs[buf][ks + tig + 4][nB + grp];
            }
#pragma unroll
            for (int mi = 0; mi < 4; mi++)
#pragma unroll
                for (int ni = 0; ni < 4; ni++)
                    MMA_TF32(acc[mi][ni], af[mi], bf[ni]);
        }
    };

    const int NT = K / BK;
    // prologue: tile 0 into buffer 0
    ldA(0); ldB(0);
    stA(0); stB(0);
    __syncthreads();

    for (int it = 0; it < NT; ++it) {
        int buf = it & 1;
        if (it + 1 < NT) { ldA((it + 1) * BK); ldB((it + 1) * BK); }
        compute(buf);
        if (it + 1 < NT) { stA(buf ^ 1); stB(buf ^ 1); }
        __syncthreads();
    }

    // epilogue
#pragma unroll
    for (int mi = 0; mi < 4; mi++) {
#pragma unroll
        for (int half = 0; half < 2; half++) {
            int gm = bm + warpM * 64 + mi * 16 + grp + half * 8;
            if (gm >= M) continue;
            float bv = BIAS ? bias[gm] : 0.0f;
            float* crow = Cb + (long long)gm * N;
#pragma unroll
            for (int ni = 0; ni < 4; ni++) {
                int gn = bn + warpN * 32 + ni * 8 + tig * 2;
                float2 v;
                v.x = acc[mi][ni][half * 2 + 0] + bv;
                v.y = acc[mi][ni][half * 2 + 1] + bv;
                *reinterpret_cast<float2*>(&crow[gn]) = v;
            }
        }
    }
}

// ---------------- row softmax (in place). flip=1: softmax(rowmax - e) ----
__global__ void __launch_bounds__(256)
softmax_rows(float* __restrict__ data, int n, int flip)
{
    __shared__ float buf[4096];
    __shared__ float red[8];
    __shared__ float bcast;
    const long long row = blockIdx.x;
    float* p = data + row * (long long)n;
    const int tid = threadIdx.x;
    const int lane = tid & 31, wid = tid >> 5;

    float m = flip ? 3.0e38f : -3.0e38f;
    for (int i = tid; i < n; i += 256) {
        float v = p[i];
        buf[i] = v;
        m = flip ? fminf(m, v) : fmaxf(m, v);
    }
#pragma unroll
    for (int o = 16; o > 0; o >>= 1) {
        float t = __shfl_xor_sync(0xffffffffu, m, o);
        m = flip ? fminf(m, t) : fmaxf(m, t);
    }
    if (lane == 0) red[wid] = m;
    __syncthreads();
    if (wid == 0) {
        float v = (lane < 8) ? red[lane] : (flip ? 3.0e38f : -3.0e38f);
#pragma unroll
        for (int o = 4; o > 0; o >>= 1) {
            float t = __shfl_xor_sync(0xffffffffu, v, o);
            v = flip ? fminf(v, t) : fmaxf(v, t);
        }
        if (lane == 0) bcast = v;
    }
    __syncthreads();
    const float mx = bcast;

    float s = 0.0f;
    for (int i = tid; i < n; i += 256) {
        float e = __expf(flip ? (mx - buf[i]) : (buf[i] - mx));
        buf[i] = e;
        s += e;
    }
#pragma unroll
    for (int o = 16; o > 0; o >>= 1) s += __shfl_xor_sync(0xffffffffu, s, o);
    if (lane == 0) red[wid] = s;
    __syncthreads();
    if (wid == 0) {
        float v = (lane < 8) ? red[lane] : 0.0f;
#pragma unroll
        for (int o = 4; o > 0; o >>= 1) v += __shfl_xor_sync(0xffffffffu, v, o);
        if (lane == 0) bcast = v;
    }
    __syncthreads();
    const float inv = 1.0f / bcast;
    for (int i = tid; i < n; i += 256) p[i] = buf[i] * inv;
}

// ---------------- epilogue: out = 2x + gp*outp + gc*outc ----------------
__global__ void __launch_bounds__(256)
combine_kernel(const float4* __restrict__ x, const float4* __restrict__ op,
               const float4* __restrict__ oc, const float* __restrict__ pg,
               const float* __restrict__ cg, float4* __restrict__ out, int n4)
{
    int i = blockIdx.x * blockDim.x + threadIdx.x;
    if (i >= n4) return;
    const float a = pg[0], b = cg[0];
    float4 xv = x[i], pv = op[i], cv = oc[i];
    float4 r;
    r.x = 2.0f * xv.x + a * pv.x + b * cv.x;
    r.y = 2.0f * xv.y + a * pv.y + b * cv.y;
    r.z = 2.0f * xv.z + a * pv.z + b * cv.z;
    r.w = 2.0f * xv.w + a * pv.w + b * cv.w;
    out[i] = r;
}

// ---------------- launch ----------------
extern "C" void kernel_launch(void* const* d_in, const int* in_sizes, int n_in,
                              void* d_out, int out_size)
{
    (void)in_sizes; (void)n_in; (void)out_size;
    const float* x       = (const float*)d_in[0];
    const float* pam_wq  = (const float*)d_in[1];
    const float* pam_bq  = (const float*)d_in[2];
    const float* pam_wk  = (const float*)d_in[3];
    const float* pam_bk  = (const float*)d_in[4];
    const float* pam_wv  = (const float*)d_in[5];
    const float* pam_bv  = (const float*)d_in[6];
    const float* pam_g   = (const float*)d_in[7];
    const float* cam_wq  = (const float*)d_in[8];
    const float* cam_bq  = (const float*)d_in[9];
    const float* cam_wk  = (const float*)d_in[10];
    const float* cam_bk  = (const float*)d_in[11];
    const float* cam_wv  = (const float*)d_in[12];
    const float* cam_bv  = (const float*)d_in[13];
    const float* cam_g   = (const float*)d_in[14];

    float *qp, *kp, *vp, *qc, *kc, *vc, *attn, *ec, *outp, *outc;
    cudaGetSymbolAddress((void**)&qp,   g_qp);
    cudaGetSymbolAddress((void**)&kp,   g_kp);
    cudaGetSymbolAddress((void**)&vp,   g_vp);
    cudaGetSymbolAddress((void**)&qc,   g_qc);
    cudaGetSymbolAddress((void**)&kc,   g_kc);
    cudaGetSymbolAddress((void**)&vc,   g_vc);
    cudaGetSymbolAddress((void**)&attn, g_attn);
    cudaGetSymbolAddress((void**)&ec,   g_ec);
    cudaGetSymbolAddress((void**)&outp, g_outp);
    cudaGetSymbolAddress((void**)&outc, g_outc);

    const long long xStr  = (long long)CCH * NPIX;
    const long long qStr  = (long long)C8  * NPIX;   // == 512*512
    const long long vStr  = (long long)CCH * NPIX;
    const long long aStrP = (long long)NPIX * NPIX;
    const long long eStrC = (long long)CCH * CCH;

    dim3 blk(256);

    // ---- 1. projections: C = W[M,512] * x[512,4096] + bias (NN) ----
    gemm_tc<false,false,true><<<dim3(NPIX/128, 1, BATCH), blk>>>(pam_wq, x, pam_bq, qp, C8,  NPIX, CCH, 0, xStr, qStr);
    gemm_tc<false,false,true><<<dim3(NPIX/128, 1, BATCH), blk>>>(pam_wk, x, pam_bk, kp, C8,  NPIX, CCH, 0, xStr, qStr);
    gemm_tc<false,false,true><<<dim3(NPIX/128, 4, BATCH), blk>>>(pam_wv, x, pam_bv, vp, CCH, NPIX, CCH, 0, xStr, vStr);
    gemm_tc<false,false,true><<<dim3(NPIX/128, 1, BATCH), blk>>>(cam_wq, x, cam_bq, qc, C8,  NPIX, CCH, 0, xStr, qStr);
    gemm_tc<false,false,true><<<dim3(NPIX/128, 1, BATCH), blk>>>(cam_wk, x, cam_bk, kc, C8,  NPIX, CCH, 0, xStr, qStr);
    gemm_tc<false,false,true><<<dim3(NPIX/128, 4, BATCH), blk>>>(cam_wv, x, cam_bv, vc, CCH, NPIX, CCH, 0, xStr, vStr);

    // ---- 2. PAM energy: E[q,k] = sum_d qp[d,q]*kp[d,k]  (TN, K=64) ----
    gemm_tc<true,false,false><<<dim3(NPIX/128, NPIX/128, BATCH), blk>>>(qp, kp, nullptr, attn,
        NPIX, NPIX, C8, qStr, qStr, aStrP);

    // ---- 3. PAM softmax over rows of 4096 ----
    softmax_rows<<<BATCH * NPIX, 256>>>(attn, NPIX, 0);

    // ---- 4. PAM AV: out[c,q] = sum_k vp[c,k]*attn[q,k]  (NT, K=4096) ----
    gemm_tc<false,true,false><<<dim3(NPIX/128, CCH/128, BATCH), blk>>>(vp, attn, nullptr, outp,
        CCH, NPIX, NPIX, vStr, aStrP, vStr);

    // ---- 5. CAM energy: E[i,j] = sum_m qc[i,m]*kc[j,m]  (NT, 512^3) ----
    gemm_tc<false,true,false><<<dim3(CCH/128, CCH/128, BATCH), blk>>>(qc, kc, nullptr, ec,
        CCH, CCH, CCH, qStr, qStr, eStrC);

    // ---- 6. CAM softmax of (rowmax - e) ----
    softmax_rows<<<BATCH * CCH, 256>>>(ec, CCH, 1);

    // ---- 7. CAM AV: out[c,n] = sum_d attn[c,d]*vc[d,n]  (NN) ----
    gemm_tc<false,false,false><<<dim3(NPIX/128, CCH/128, BATCH), blk>>>(ec, vc, nullptr, outc,
        CCH, NPIX, CCH, eStrC, vStr, vStr);

    // ---- 8. combine ----
    const int n4 = (BATCH * CCH * NPIX) / 4;
    combine_kernel<<<(n4 + 255) / 256, 256>>>((const float4*)x, (const float4*)outp,
        (const float4*)outc, pam_g, cam_g, (float4*)d_out, n4);
}